// round 10
// baseline (speedup 1.0000x reference)
#include <cuda_runtime.h>
#include <cuda_bf16.h>
#include <stdint.h>

#define BB 64
#define HH 512
#define WW 512
#define CC 3
#define ROWF (WW * CC)     // 1536 floats per row
#define ROWV (ROWF / 4)    // 384 float4 per row
#define TPB 128            // threads per block
#define CPT 3              // column chunks per thread (TPB*CPT == ROWV)
#define RPB 4              // rows per block

__global__ __launch_bounds__(TPB, 8) void cutmix_kernel(
    const float* __restrict__ x,
    const int*   __restrict__ y1,
    const int*   __restrict__ y2,
    const int*   __restrict__ x1,
    const int*   __restrict__ x2,
    const int*   __restrict__ perm,
    float*       __restrict__ out)
{
    // h-major ordering preserved: consecutive blocks -> same rows, different
    // image, so donor-box reads hit L2 lines fetched within the same wave.
    const int b  = blockIdx.x & (BB - 1);
    const int h0 = (blockIdx.x >> 6) * RPB;

    const int ya = y1[b];
    const int yb = y2[b];
    const int xa = x1[b];
    const int xb = x2[b];
    const int pb = perm[b];

    const int t = threadIdx.x;           // 0 .. 127

    const float4* __restrict__ xv = reinterpret_cast<const float4*>(x);
    float4* __restrict__ ov = reinterpret_cast<float4*>(out);

    // 32-bit indexing; donor as single unsigned delta (exact mod 2^32).
    const uint32_t selfIdx    = ((uint32_t)b * HH + h0) * ROWV + (uint32_t)t;
    const uint32_t donorDelta = (uint32_t)(pb - b) * (uint32_t)(HH * ROWV);

    // Per-chunk x-predicates (chunk c covers float4 index t + c*TPB).
    bool pe[CPT];       // chunk fully/partly inside at its first element
    bool uni[CPT];      // chunk does not straddle the x1/x2 boundary
    #pragma unroll
    for (int c = 0; c < CPT; c++) {
        const int jj = (t + c * TPB) * 4;
        const int w0 = jj / 3;
        const int w1 = (jj + 3) / 3;
        const bool q0 = (w0 >= xa) & (w0 < xb);
        const bool q1 = (w1 >= xa) & (w1 < xb);
        pe[c]  = q0;
        uni[c] = (q0 == q1);
    }

    float4 v[RPB][CPT];

    if (uni[0] & uni[1] & uni[2]) {
        // Fast path: 12 independent loads, all front-batched (MLP_p1 = 12),
        // source selected per (row, chunk) by address only.
        #pragma unroll
        for (int r = 0; r < RPB; r++) {
            const int h = h0 + r;
            const bool hin = (h >= ya) & (h < yb);
            #pragma unroll
            for (int c = 0; c < CPT; c++) {
                const uint32_t idx = selfIdx + (uint32_t)(r * ROWV + c * TPB)
                                   + ((hin & pe[c]) ? donorDelta : 0u);
                v[r][c] = __ldg(&xv[idx]);
            }
        }
    } else {
        // Straddle path (warps containing a box-edge chunk only): load both
        // sources for in-box rows and blend element-wise. Correct for
        // uniform chunks too (predicates just agree).
        #pragma unroll
        for (int r = 0; r < RPB; r++) {
            const int h = h0 + r;
            const bool hin = (h >= ya) & (h < yb);
            #pragma unroll
            for (int c = 0; c < CPT; c++) {
                const uint32_t idx = selfIdx + (uint32_t)(r * ROWV + c * TPB);
                float4 a = xv[idx];
                if (hin) {
                    float4 s = xv[idx + donorDelta];
                    const float* af = reinterpret_cast<const float*>(&a);
                    const float* sf = reinterpret_cast<const float*>(&s);
                    const int jj = (t + c * TPB) * 4;
                    float rr[4];
                    #pragma unroll
                    for (int k = 0; k < 4; k++) {
                        const int w = (jj + k) / 3;
                        const bool p = (w >= xa) & (w < xb);
                        rr[k] = p ? sf[k] : af[k];
                    }
                    a = make_float4(rr[0], rr[1], rr[2], rr[3]);
                }
                v[r][c] = a;
            }
        }
    }

    #pragma unroll
    for (int r = 0; r < RPB; r++) {
        #pragma unroll
        for (int c = 0; c < CPT; c++) {
            __stcs(&ov[selfIdx + (uint32_t)(r * ROWV + c * TPB)], v[r][c]);
        }
    }
}

extern "C" void kernel_launch(void* const* d_in, const int* in_sizes, int n_in,
                              void* d_out, int out_size)
{
    const float* x    = (const float*)d_in[0];
    const int*   y1   = (const int*)  d_in[1];
    const int*   y2   = (const int*)  d_in[2];
    const int*   x1   = (const int*)  d_in[3];
    const int*   x2   = (const int*)  d_in[4];
    const int*   perm = (const int*)  d_in[5];
    float*       out  = (float*)      d_out;

    (void)in_sizes; (void)n_in; (void)out_size;

    cutmix_kernel<<<(BB * HH) / RPB, TPB>>>(x, y1, y2, x1, x2, perm, out);
}

// round 11
// speedup vs baseline: 1.0689x; 1.0689x over previous
#include <cuda_runtime.h>
#include <cuda_bf16.h>
#include <stdint.h>

#define BB 64
#define HH 512
#define WW 512
#define CC 3
#define ROWF (WW * CC)     // 1536 floats per row
#define ROWV (ROWF / 4)    // 384 float4 per row
#define RPB 4              // rows per block

__global__ __launch_bounds__(ROWV) void cutmix_kernel(
    const float* __restrict__ x,
    const int*   __restrict__ y1,
    const int*   __restrict__ y2,
    const int*   __restrict__ x1,
    const int*   __restrict__ x2,
    const int*   __restrict__ perm,
    float*       __restrict__ out)
{
    // h-major ordering: consecutive blocks -> same row group, different image.
    // One wave covers a row band of ALL images, so donor-box reads hit L2
    // lines fetched by the donor image's own block in the same wave.
    const int b  = blockIdx.x & (BB - 1);
    const int h0 = (blockIdx.x >> 6) * RPB;

    // Per-block scalar metadata (L2-resident, uniform across block)
    const int ya = __ldg(&y1[b]);
    const int yb = __ldg(&y2[b]);
    const int xa = __ldg(&x1[b]);
    const int xb = __ldg(&x2[b]);
    const int pb = __ldg(&perm[b]);

    const int t  = threadIdx.x;          // 0 .. 383
    const int j  = t * 4;                // first float index in row
    const int w0 = j / 3;                // pixel of first element
    const int w1 = (j + 3) / 3;          // pixel of last element

    const bool p0 = (w0 >= xa) & (w0 < xb);
    const bool p1 = (w1 >= xa) & (w1 < xb);

    const float4* __restrict__ xv = reinterpret_cast<const float4*>(x);
    float4* __restrict__ ov = reinterpret_cast<float4*>(out);

    float4 v[RPB];

    if (p0 == p1) {
        // Uniform chunk: one vector load per row, source row selected by
        // address. All RPB loads issued before any store (front-batched MLP).
        #pragma unroll
        for (int r = 0; r < RPB; r++) {
            const int h = h0 + r;
            const bool hin = (h >= ya) & (h < yb);
            const int sb = (hin & p0) ? pb : b;
            v[r] = __ldg(&xv[((size_t)sb * HH + h) * ROWV + t]);
        }
    } else {
        // Chunk straddles x1/x2 boundary (2 of 384 threads per row): blend.
        #pragma unroll
        for (int r = 0; r < RPB; r++) {
            const int h = h0 + r;
            const bool hin = (h >= ya) & (h < yb);
            float4 a = xv[((size_t)b * HH + h) * ROWV + t];
            if (hin) {
                float4 s = xv[((size_t)pb * HH + h) * ROWV + t];
                const float* af = reinterpret_cast<const float*>(&a);
                const float* sf = reinterpret_cast<const float*>(&s);
                float rr[4];
                #pragma unroll
                for (int k = 0; k < 4; k++) {
                    const int w = (j + k) / 3;
                    const bool p = (w >= xa) & (w < xb);
                    rr[k] = p ? sf[k] : af[k];
                }
                a = make_float4(rr[0], rr[1], rr[2], rr[3]);
            }
            v[r] = a;
        }
    }

    // Evict-first stores: output is never re-read; keep L2 capacity for the
    // input tensor (donor-box hits within a wave + cross-replay residency).
    #pragma unroll
    for (int r = 0; r < RPB; r++) {
        const int h = h0 + r;
        __stcs(&ov[((size_t)b * HH + h) * ROWV + t], v[r]);
    }
}

extern "C" void kernel_launch(void* const* d_in, const int* in_sizes, int n_in,
                              void* d_out, int out_size)
{
    const float* x    = (const float*)d_in[0];
    const int*   y1   = (const int*)  d_in[1];
    const int*   y2   = (const int*)  d_in[2];
    const int*   x1   = (const int*)  d_in[3];
    const int*   x2   = (const int*)  d_in[4];
    const int*   perm = (const int*)  d_in[5];
    float*       out  = (float*)      d_out;

    (void)in_sizes; (void)n_in; (void)out_size;

    cutmix_kernel<<<(BB * HH) / RPB, ROWV>>>(x, y1, y2, x1, x2, perm, out);
}

// round 12
// speedup vs baseline: 1.0729x; 1.0038x over previous
#include <cuda_runtime.h>
#include <cuda_bf16.h>
#include <stdint.h>

#define BB 64
#define HH 512
#define WW 512
#define CC 3
#define ROWF (WW * CC)     // 1536 floats per row
#define ROWV (ROWF / 4)    // 384 float4 per row
#define RPB 4              // rows per block

__global__ __launch_bounds__(ROWV) void cutmix_kernel(
    const float* __restrict__ x,
    const int*   __restrict__ y1,
    const int*   __restrict__ y2,
    const int*   __restrict__ x1,
    const int*   __restrict__ x2,
    const int*   __restrict__ perm,
    float*       __restrict__ out)
{
    // h-major ordering: consecutive blocks -> same row group, different image.
    // One wave covers a row band of ALL images, so donor-box reads hit L2
    // lines fetched by the donor image's own block in the same wave.
    const int b  = blockIdx.x & (BB - 1);
    const int h0 = (blockIdx.x >> 6) * RPB;

    // Per-block scalar metadata (L2-resident, uniform across block)
    const int ya = __ldg(&y1[b]);
    const int yb = __ldg(&y2[b]);
    const int xa = __ldg(&x1[b]);
    const int xb = __ldg(&x2[b]);
    const int pb = __ldg(&perm[b]);

    const int t  = threadIdx.x;          // 0 .. 383
    const int j  = t * 4;                // first float index in row
    const int w0 = j / 3;                // pixel of first element
    const int w1 = (j + 3) / 3;          // pixel of last element

    const bool p0 = (w0 >= xa) & (w0 < xb);
    const bool p1 = (w1 >= xa) & (w1 < xb);

    const float4* __restrict__ xv = reinterpret_cast<const float4*>(x);
    float4* __restrict__ ov = reinterpret_cast<float4*>(out);

    float4 v[RPB];

    if (p0 == p1) {
        // Uniform chunk: one vector load per row, source row selected by
        // address. All RPB loads issued before any store (front-batched MLP).
        #pragma unroll
        for (int r = 0; r < RPB; r++) {
            const int h = h0 + r;
            const bool hin = (h >= ya) & (h < yb);
            const int sb = (hin & p0) ? pb : b;
            v[r] = __ldg(&xv[((size_t)sb * HH + h) * ROWV + t]);
        }
    } else {
        // Chunk straddles x1/x2 boundary (2 of 384 threads per row): blend.
        #pragma unroll
        for (int r = 0; r < RPB; r++) {
            const int h = h0 + r;
            const bool hin = (h >= ya) & (h < yb);
            float4 a = xv[((size_t)b * HH + h) * ROWV + t];
            if (hin) {
                float4 s = xv[((size_t)pb * HH + h) * ROWV + t];
                const float* af = reinterpret_cast<const float*>(&a);
                const float* sf = reinterpret_cast<const float*>(&s);
                float rr[4];
                #pragma unroll
                for (int k = 0; k < 4; k++) {
                    const int w = (j + k) / 3;
                    const bool p = (w >= xa) & (w < xb);
                    rr[k] = p ? sf[k] : af[k];
                }
                a = make_float4(rr[0], rr[1], rr[2], rr[3]);
            }
            v[r] = a;
        }
    }

    // Write-through stores: do NOT allocate L2 lines for the output stream.
    // The output is never re-read; keeping all 126 MB of L2 as a read cache
    // for x maximizes cross-replay input residency (measured ~90 MB/replay
    // of reads already served by L2 — this protects and extends that).
    #pragma unroll
    for (int r = 0; r < RPB; r++) {
        const int h = h0 + r;
        __stwt(&ov[((size_t)b * HH + h) * ROWV + t], v[r]);
    }
}

extern "C" void kernel_launch(void* const* d_in, const int* in_sizes, int n_in,
                              void* d_out, int out_size)
{
    const float* x    = (const float*)d_in[0];
    const int*   y1   = (const int*)  d_in[1];
    const int*   y2   = (const int*)  d_in[2];
    const int*   x1   = (const int*)  d_in[3];
    const int*   x2   = (const int*)  d_in[4];
    const int*   perm = (const int*)  d_in[5];
    float*       out  = (float*)      d_out;

    (void)in_sizes; (void)n_in; (void)out_size;

    cutmix_kernel<<<(BB * HH) / RPB, ROWV>>>(x, y1, y2, x1, x2, perm, out);
}

// round 13
// speedup vs baseline: 1.0770x; 1.0038x over previous
#include <cuda_runtime.h>
#include <cuda_bf16.h>
#include <stdint.h>

#define BB 64
#define HH 512
#define WW 512
#define CC 3
#define ROWF (WW * CC)     // 1536 floats per row
#define ROWV (ROWF / 4)    // 384 float4 per row
#define RPB 4              // rows per block

__global__ __launch_bounds__(ROWV) void cutmix_kernel(
    const float* __restrict__ x,
    const int*   __restrict__ y1,
    const int*   __restrict__ y2,
    const int*   __restrict__ x1,
    const int*   __restrict__ x2,
    const int*   __restrict__ perm,
    float*       __restrict__ out)
{
    // h-major ordering: consecutive blocks -> same row group, different image.
    // One wave covers a row band of ALL images, so donor-box reads hit L2
    // lines fetched by the donor image's own block in the same wave.
    const int b  = blockIdx.x & (BB - 1);
    const int h0 = (blockIdx.x >> 6) * RPB;

    // Per-block scalar metadata (L2-resident, uniform across block)
    const int ya = __ldg(&y1[b]);
    const int yb = __ldg(&y2[b]);
    const int xa = __ldg(&x1[b]);
    const int xb = __ldg(&x2[b]);
    const int pb = __ldg(&perm[b]);

    const int t  = threadIdx.x;          // 0 .. 383
    const int j  = t * 4;                // first float index in row
    const int w0 = j / 3;                // pixel of first element
    const int w1 = (j + 3) / 3;          // pixel of last element

    const bool p0 = (w0 >= xa) & (w0 < xb);
    const bool p1 = (w1 >= xa) & (w1 < xb);

    const float4* __restrict__ xv = reinterpret_cast<const float4*>(x);
    float4* __restrict__ ov = reinterpret_cast<float4*>(out);

    float4 v[RPB];

    if (p0 == p1) {
        // Uniform chunk: one vector load per row, source row selected by
        // address. All RPB loads issued before any store (front-batched MLP).
        #pragma unroll
        for (int r = 0; r < RPB; r++) {
            const int h = h0 + r;
            const bool hin = (h >= ya) & (h < yb);
            const int sb = (hin & p0) ? pb : b;
            v[r] = __ldg(&xv[((size_t)sb * HH + h) * ROWV + t]);
        }
    } else {
        // Chunk straddles x1/x2 boundary (2 of 384 threads per row): blend.
        #pragma unroll
        for (int r = 0; r < RPB; r++) {
            const int h = h0 + r;
            const bool hin = (h >= ya) & (h < yb);
            float4 a = xv[((size_t)b * HH + h) * ROWV + t];
            if (hin) {
                float4 s = xv[((size_t)pb * HH + h) * ROWV + t];
                const float* af = reinterpret_cast<const float*>(&a);
                const float* sf = reinterpret_cast<const float*>(&s);
                float rr[4];
                #pragma unroll
                for (int k = 0; k < 4; k++) {
                    const int w = (j + k) / 3;
                    const bool p = (w >= xa) & (w < xb);
                    rr[k] = p ? sf[k] : af[k];
                }
                a = make_float4(rr[0], rr[1], rr[2], rr[3]);
            }
            v[r] = a;
        }
    }

    // Write-through stores: do not allocate L2 lines for the output stream;
    // output is never re-read, so L2 stays a read cache for x (intra-wave
    // donor hits + cross-replay residency).
    #pragma unroll
    for (int r = 0; r < RPB; r++) {
        const int h = h0 + r;
        __stwt(&ov[((size_t)b * HH + h) * ROWV + t], v[r]);
    }
}

extern "C" void kernel_launch(void* const* d_in, const int* in_sizes, int n_in,
                              void* d_out, int out_size)
{
    const float* x    = (const float*)d_in[0];
    const int*   y1   = (const int*)  d_in[1];
    const int*   y2   = (const int*)  d_in[2];
    const int*   x1   = (const int*)  d_in[3];
    const int*   x2   = (const int*)  d_in[4];
    const int*   perm = (const int*)  d_in[5];
    float*       out  = (float*)      d_out;

    (void)in_sizes; (void)n_in; (void)out_size;

    cutmix_kernel<<<(BB * HH) / RPB, ROWV>>>(x, y1, y2, x1, x2, perm, out);
}